// round 2
// baseline (speedup 1.0000x reference)
#include <cuda_runtime.h>
#include <cstdint>

#define ACT_F (4.0f/3.0f)
#define SMEM_BYTES (131072 + 65536 + 16384 + 4096 + 2048)

// ---------------- device-global scratch (no allocations allowed) ----------------
__device__ float g_s[5];                       // s1a, s1b, s2, s3, sout
__device__ unsigned short g_l1a[128*1024];
__device__ unsigned short g_l1b[128*1024];
__device__ unsigned short g_l2 [128*512];
__device__ unsigned short g_l3 [64*128];
__device__ unsigned short g_l4 [128*64];
__device__ int g_c1a[128], g_p1a[128];
__device__ int g_c1b[128], g_p1b[128];
__device__ int g_c2[128];
__device__ int g_c3[64];
__device__ int g_c4[128];

// ---------------- prep kernel 1: per-matrix max|w| ----------------
__global__ void k_scales(const float* W1a, const float* W1b, const float* W2,
                         const float* W3, const float* W4) {
  __shared__ float red[8];
  const float* ptrs[5] = {W1a, W1b, W2, W3, W4};
  const int ns[5] = {131072, 131072, 65536, 8192, 8192};
  int m = blockIdx.x;
  const float* p = ptrs[m];
  int n = ns[m];
  float mx = 0.f;
  for (int i = threadIdx.x; i < n; i += 256) mx = fmaxf(mx, fabsf(p[i]));
  for (int o = 16; o; o >>= 1) mx = fmaxf(mx, __shfl_xor_sync(0xffffffffu, mx, o));
  if ((threadIdx.x & 31) == 0) red[threadIdx.x >> 5] = mx;
  __syncthreads();
  if (threadIdx.x < 8) {
    mx = red[threadIdx.x];
    for (int o = 4; o; o >>= 1) mx = fmaxf(mx, __shfl_xor_sync(0xffu, mx, o));
    if (threadIdx.x == 0) g_s[m] = mx;
  }
}

// ---------------- prep kernel 2: ternary sparse index lists ----------------
// One thread per output row; indices stored ascending, sign in bit 15.
// For W1 matrices, record split = #entries with idx < 512 (chunking).
__global__ void k_lists(const float* W1a, const float* W1b, const float* W2,
                        const float* W3, const float* W4) {
  int m = blockIdx.x, row = threadIdx.x;
  const float* ptrs[5] = {W1a, W1b, W2, W3, W4};
  const int len[5]  = {1024, 1024, 512, 128, 64};
  const int rows[5] = {128, 128, 128, 64, 128};
  unsigned short* const lst[5] = {g_l1a, g_l1b, g_l2, g_l3, g_l4};
  int* const cnt[5] = {g_c1a, g_c1b, g_c2, g_c3, g_c4};
  if (row >= rows[m]) return;
  float s = g_s[m];
  const float* w = ptrs[m] + row * len[m];
  unsigned short* L = lst[m] + row * len[m];
  int c = 0;
  for (int i = 0; i < len[m]; ++i) {
    if (m < 2 && i == 512) { if (m == 0) g_p1a[row] = c; else g_p1b[row] = c; }
    float q = rintf(w[i] / s);          // identical to reference quant_weight
    if (q != 0.f) L[c++] = (unsigned short)(i | (q < 0.f ? 0x8000u : 0u));
  }
  cnt[m][row] = c;
}

// ---------------- main fused kernel ----------------
// CTA = 32 batch rows (lane == row). 8 chunks of [32 x 512] fp32 loaded via
// cp.async double-buffer, transposed into swizzled xT (bank = row ^ (col&31)),
// then conflict-free lane-parallel sparse gathers for all 4 layers.
__device__ __forceinline__ void prefetch_chunk(const float* xblk, int c,
                                               float* stg, int tid) {
  const float* src = xblk + (c >> 1) * 1024 + (c & 1) * 512;
#pragma unroll
  for (int i = 0; i < 16; ++i) {
    int f4 = tid + 256 * i;            // float4 index 0..4095
    int row = f4 >> 7;                 // 128 float4 per row
    int c4 = f4 & 127;
    const float* g = src + row * 4096 + c4 * 4;
    unsigned sa = (unsigned)__cvta_generic_to_shared(stg + row * 512 + c4 * 4);
    asm volatile("cp.async.cg.shared.global [%0], [%1], 16;\n" :: "r"(sa), "l"(g));
  }
  asm volatile("cp.async.commit_group;\n");
}

__global__ void __launch_bounds__(256, 1) k_main(
    const float* __restrict__ x,
    const float* __restrict__ b1a, const float* __restrict__ b1b,
    const float* __restrict__ b2,  const float* __restrict__ b3,
    float* __restrict__ out) {
  extern __shared__ float smem[];
  float* stage0 = smem;                         // 32*512 f32 = 64KB
  float* stage1 = smem + 32 * 512;              // 64KB
  float* xT     = smem + 2 * 32 * 512;          // 512*32 f32 swizzled = 64KB
  unsigned char* hT  = (unsigned char*)(xT + 512 * 32);  // 512*32 u8
  unsigned char* h2T = hT + 512 * 32;                     // 128*32 u8
  unsigned char* h3T = h2T + 128 * 32;                    //  64*32 u8
  float* outT = (float*)hT;                     // alias (hT/h2T dead by layer 4)

  int tid = threadIdx.x, lane = tid & 31, warp = tid >> 5;
  const float* xblk = x + (size_t)blockIdx.x * 32 * 4096;

  prefetch_chunk(xblk, 0, stage0, tid);
  prefetch_chunk(xblk, 1, stage1, tid);

  float acc[16];
#pragma unroll 1
  for (int c = 0; c < 8; ++c) {
    int br = c >> 1, half = c & 1;
    float* stg = (c & 1) ? stage1 : stage0;
    if (c < 7) asm volatile("cp.async.wait_group 1;\n" ::: "memory");
    else       asm volatile("cp.async.wait_group 0;\n" ::: "memory");
    __syncthreads();

    // transpose stage -> xT (both sides bank-conflict-free)
#pragma unroll 4
    for (int i = 0; i < 64; ++i) {
      int q = warp + 8 * i;            // 0..511 work items
      int row = q & 31, cb = q >> 5;
      int col = cb * 32 + lane;
      xT[col * 32 + (row ^ lane)] = stg[row * 512 + col];
    }
    __syncthreads();
    if (c + 2 < 8) prefetch_chunk(xblk, c + 2, stg, tid);

    if (half == 0) {
#pragma unroll
      for (int j0 = 0; j0 < 16; ++j0) acc[j0] = 0.f;
    }
    const unsigned short* L = (br & 1) ? g_l1b : g_l1a;
    const int* CNT = (br & 1) ? g_c1b : g_c1a;
    const int* SPL = (br & 1) ? g_p1b : g_p1a;
#pragma unroll
    for (int j0 = 0; j0 < 16; ++j0) {
      int j = warp * 16 + j0;
      int k0 = half ? SPL[j] : 0;
      int k1 = half ? CNT[j] : SPL[j];
      const unsigned short* lj = L + j * 1024;
      float a0 = 0.f, a1 = 0.f;
      int k = k0;
      for (; k + 2 <= k1; k += 2) {
        unsigned e0 = lj[k], e1 = lj[k + 1];
        float v0 = xT[(e0 & 511u) * 32u + (lane ^ (e0 & 31u))];
        float v1 = xT[(e1 & 511u) * 32u + (lane ^ (e1 & 31u))];
        a0 += (e0 & 0x8000u) ? -v0 : v0;
        a1 += (e1 & 0x8000u) ? -v1 : v1;
      }
      if (k < k1) {
        unsigned e0 = lj[k];
        float v0 = xT[(e0 & 511u) * 32u + (lane ^ (e0 & 31u))];
        a0 += (e0 & 0x8000u) ? -v0 : v0;
      }
      acc[j0] += a0 + a1;
    }
    if (half == 1) {                    // finish branch: bias + quant_relu
      const float* bb = (br & 1) ? b1b : b1a;
      float s = (br & 1) ? g_s[1] : g_s[0];
#pragma unroll
      for (int j0 = 0; j0 < 16; ++j0) {
        int j = warp * 16 + j0;
        float z = s * acc[j0] + bb[j];
        float n = fminf(fmaxf(rintf(z / ACT_F), 0.f), 3.f);
        hT[(br * 128 + j) * 32 + lane] = (unsigned char)n;
      }
    }
    __syncthreads();
  }

  // layer 2: h[512] -> 128, integer gather-sums
  {
    float s2 = g_s[2];
#pragma unroll
    for (int j0 = 0; j0 < 16; ++j0) {
      int j = warp * 16 + j0;
      const unsigned short* lj = g_l2 + j * 512;
      int k1 = g_c2[j];
      int m = 0;
      for (int k = 0; k < k1; ++k) {
        unsigned e = lj[k];
        int v = hT[(e & 511u) * 32u + lane];
        m += (e & 0x8000u) ? -v : v;
      }
      float z = s2 * (ACT_F * (float)m) + b2[j];
      float n = fminf(fmaxf(rintf(z / ACT_F), 0.f), 3.f);
      h2T[j * 32 + lane] = (unsigned char)n;
    }
  }
  __syncthreads();
  // layer 3: 128 -> 64
  {
    float s3 = g_s[3];
#pragma unroll
    for (int j0 = 0; j0 < 8; ++j0) {
      int j = warp * 8 + j0;
      const unsigned short* lj = g_l3 + j * 128;
      int k1 = g_c3[j];
      int m = 0;
      for (int k = 0; k < k1; ++k) {
        unsigned e = lj[k];
        int v = h2T[(e & 127u) * 32u + lane];
        m += (e & 0x8000u) ? -v : v;
      }
      float z = s3 * (ACT_F * (float)m) + b3[j];
      float n = fminf(fmaxf(rintf(z / ACT_F), 0.f), 3.f);
      h3T[j * 32 + lane] = (unsigned char)n;
    }
  }
  __syncthreads();
  // layer 4: 64 -> 128 (no bias, no quant), staged for coalesced store
  {
    float s4 = g_s[4];
#pragma unroll
    for (int j0 = 0; j0 < 16; ++j0) {
      int j = warp * 16 + j0;
      const unsigned short* lj = g_l4 + j * 64;
      int k1 = g_c4[j];
      int m = 0;
      for (int k = 0; k < k1; ++k) {
        unsigned e = lj[k];
        int v = h3T[(e & 63u) * 32u + lane];
        m += (e & 0x8000u) ? -v : v;
      }
      outT[j * 33 + lane] = s4 * (ACT_F * (float)m);
    }
  }
  __syncthreads();
  float* og = out + (size_t)blockIdx.x * 32 * 128;
#pragma unroll
  for (int p = 0; p < 16; ++p) {
    int lin = tid + 256 * p;
    int row = lin >> 7, col = lin & 127;
    og[row * 128 + col] = outT[col * 33 + row];
  }
}

extern "C" void kernel_launch(void* const* d_in, const int* in_sizes, int n_in,
                              void* d_out, int out_size) {
  const float* x   = (const float*)d_in[0];
  const float* W1a = (const float*)d_in[1];
  const float* b1a = (const float*)d_in[2];
  const float* W1b = (const float*)d_in[3];
  const float* b1b = (const float*)d_in[4];
  const float* W2  = (const float*)d_in[5];
  const float* b2  = (const float*)d_in[6];
  const float* W3  = (const float*)d_in[7];
  const float* b3  = (const float*)d_in[8];
  const float* W4  = (const float*)d_in[9];
  float* out = (float*)d_out;

  cudaFuncSetAttribute(k_main, cudaFuncAttributeMaxDynamicSharedMemorySize,
                       SMEM_BYTES);
  k_scales<<<5, 256>>>(W1a, W1b, W2, W3, W4);
  k_lists<<<5, 128>>>(W1a, W1b, W2, W3, W4);
  k_main<<<1024, 256, SMEM_BYTES>>>(x, b1a, b1b, b2, b3, out);
}

// round 4
// speedup vs baseline: 1.2433x; 1.2433x over previous
#include <cuda_runtime.h>
#include <cstdint>

#define ACT_F (4.0f/3.0f)

// ---- one contiguous packed pool (u16: idx | sign<<15), dynamic regions ----
#define NPACK 16384        // 32768 B pool; expected total nnz ~7.4K (2.2x headroom)
// ---- boundary array (ints), values are GLOBAL offsets into the pool ----
#define BND1A 0            // 128*5 (row start + 3 sub-splits + end)
#define BND1B 640          // 128*5
#define OFF2  1280         // 129
#define OFF3  1409         // 65
#define OFF4  1474         // 129
#define NBND_AL 1664       // padded to 16B multiple (6656 B)

__device__ unsigned g_sbits[5];
__device__ __align__(16) unsigned short g_packed[NPACK];
__device__ __align__(16) int g_bnd[NBND_AL];
__device__ int g_cntA[128*4], g_cntB[128*4], g_cnt2[128], g_cnt3[64], g_cnt4[128];

// ---------------- prep 0: zero scale bits ----------------
__global__ void k_init() { if (threadIdx.x < 5) g_sbits[threadIdx.x] = 0u; }

// ---------------- prep 1: per-matrix max|w| (parallel, atomicMax on bits) ----
__global__ void k_scales(const float* W1a, const float* W1b, const float* W2,
                         const float* W3, const float* W4) {
  __shared__ float red[8];
  const float* ptrs[5] = {W1a, W1b, W2, W3, W4};
  const int ns[5] = {131072, 131072, 65536, 8192, 8192};
  int m = blockIdx.x >> 4, slice = blockIdx.x & 15;
  int n4 = ns[m] >> 2;
  int per = (n4 + 15) >> 4;
  int lo = slice * per;
  int hi = lo + per; if (hi > n4) hi = n4;
  const float4* p = (const float4*)ptrs[m];
  float mx = 0.f;
  for (int i = lo + threadIdx.x; i < hi; i += 256) {
    float4 v = p[i];
    mx = fmaxf(mx, fmaxf(fmaxf(fabsf(v.x), fabsf(v.y)), fmaxf(fabsf(v.z), fabsf(v.w))));
  }
  for (int o = 16; o; o >>= 1) mx = fmaxf(mx, __shfl_xor_sync(0xffffffffu, mx, o));
  if ((threadIdx.x & 31) == 0) red[threadIdx.x >> 5] = mx;
  __syncthreads();
  if (threadIdx.x < 8) {
    mx = red[threadIdx.x];
    for (int o = 4; o; o >>= 1) mx = fmaxf(mx, __shfl_xor_sync(0xffu, mx, o));
    if (threadIdx.x == 0) atomicMax(&g_sbits[m], __float_as_uint(mx));
  }
}

// warp -> (matrix, row) decode; 576 rows total
__device__ __forceinline__ void decode(int gw, int& m, int& row) {
  if (gw < 128)      { m = 0; row = gw; }
  else if (gw < 256) { m = 1; row = gw - 128; }
  else if (gw < 384) { m = 2; row = gw - 256; }
  else if (gw < 448) { m = 3; row = gw - 384; }
  else               { m = 4; row = gw - 448; }
}

// ---------------- prep 2: count nnz per row (per-sub for layer1) ----------------
__global__ void k_count(const float* W1a, const float* W1b, const float* W2,
                        const float* W3, const float* W4) {
  int gw = blockIdx.x * 8 + (threadIdx.x >> 5);
  int lane = threadIdx.x & 31;
  int m, row; decode(gw, m, row);
  const float* ptrs[5] = {W1a, W1b, W2, W3, W4};
  const int lens[5] = {1024, 1024, 512, 128, 64};
  float s = __uint_as_float(g_sbits[m]);
  const float* w = ptrs[m] + row * lens[m];
  int nit = lens[m] >> 5;
  int c[4] = {0, 0, 0, 0};
  for (int t = 0; t < nit; ++t) {
    float v = w[t * 32 + lane];
    float q = rintf(v / s);
    unsigned mk = __ballot_sync(0xffffffffu, q != 0.f);
    c[(m < 2) ? (t >> 3) : 0] += __popc(mk);
  }
  if (lane == 0) {
    if (m == 0)      { for (int k = 0; k < 4; ++k) g_cntA[row * 4 + k] = c[k]; }
    else if (m == 1) { for (int k = 0; k < 4; ++k) g_cntB[row * 4 + k] = c[k]; }
    else if (m == 2) g_cnt2[row] = c[0];
    else if (m == 3) g_cnt3[row] = c[0];
    else             g_cnt4[row] = c[0];
  }
}

// ---------------- prep 3: prefix scans -> GLOBAL boundary offsets ----------------
__global__ void k_offsets() {
  __shared__ int sc[1344];
  __shared__ int segbase[6];
  int tid = threadIdx.x;
  for (int i = tid; i < 1344; i += 256) {
    int v;
    if (i < 512)        v = g_cntA[i];
    else if (i < 1024)  v = g_cntB[i - 512];
    else if (i < 1152)  v = g_cnt2[i - 1024];
    else if (i < 1216)  v = g_cnt3[i - 1152];
    else                v = g_cnt4[i - 1216];
    sc[i] = v;
  }
  __syncthreads();
  int warp = tid >> 5, lane = tid & 31;
  const int segb[5] = {0, 512, 1024, 1152, 1216};
  const int segn[5] = {512, 512, 128, 64, 128};
  if (warp < 5) {
    int base = segb[warp], n = segn[warp], carry = 0;
    for (int cks = 0; cks < n; cks += 32) {
      int v = sc[base + cks + lane];
      for (int o = 1; o < 32; o <<= 1) {
        int t = __shfl_up_sync(0xffffffffu, v, o);
        if (lane >= o) v += t;
      }
      v += carry;
      sc[base + cks + lane] = v;
      carry = __shfl_sync(0xffffffffu, v, 31);
    }
  }
  __syncthreads();
  if (tid == 0) {            // dynamic segment bases (contiguous packing)
    int b = 0;
    segbase[0] = 0;
    const int segend[5] = {511, 1023, 1151, 1215, 1343};
    for (int s2 = 0; s2 < 5; ++s2) { b += sc[segend[s2]]; segbase[s2 + 1] = b; }
  }
  __syncthreads();
  for (int i = tid; i < 640; i += 256) {
    int r = i / 5, cpos = i % 5;
    int v = (cpos == 0) ? (r ? sc[r * 4 - 1] : 0) : sc[r * 4 + cpos - 1];
    g_bnd[BND1A + i] = segbase[0] + v;
  }
  for (int i = tid; i < 640; i += 256) {
    int r = i / 5, cpos = i % 5;
    int v = (cpos == 0) ? (r ? sc[512 + r * 4 - 1] : 0) : sc[512 + r * 4 + cpos - 1];
    g_bnd[BND1B + i] = segbase[1] + v;
  }
  for (int i = tid; i < 129; i += 256) g_bnd[OFF2 + i] = segbase[2] + (i ? sc[1024 + i - 1] : 0);
  for (int i = tid; i < 65;  i += 256) g_bnd[OFF3 + i] = segbase[3] + (i ? sc[1152 + i - 1] : 0);
  for (int i = tid; i < 129; i += 256) g_bnd[OFF4 + i] = segbase[4] + (i ? sc[1216 + i - 1] : 0);
  for (int i = 1603 + tid; i < NBND_AL; i += 256) g_bnd[i] = 0;  // pad defined
}

// ---------------- prep 4: fill packed CSR via ballot compaction ----------------
__global__ void k_fill(const float* W1a, const float* W1b, const float* W2,
                       const float* W3, const float* W4) {
  int gw = blockIdx.x * 8 + (threadIdx.x >> 5);
  int lane = threadIdx.x & 31;
  int m, row; decode(gw, m, row);
  const float* ptrs[5] = {W1a, W1b, W2, W3, W4};
  const int lens[5] = {1024, 1024, 512, 128, 64};
  float s = __uint_as_float(g_sbits[m]);
  const float* w = ptrs[m] + row * lens[m];
  int pos;
  if (m == 0)      pos = g_bnd[BND1A + row * 5];
  else if (m == 1) pos = g_bnd[BND1B + row * 5];
  else if (m == 2) pos = g_bnd[OFF2 + row];
  else if (m == 3) pos = g_bnd[OFF3 + row];
  else             pos = g_bnd[OFF4 + row];
  int nit = lens[m] >> 5;
  for (int t = 0; t < nit; ++t) {
    int idx = t * 32 + lane;
    float v = w[idx];
    float q = rintf(v / s);
    bool nz = (q != 0.f);
    unsigned mk = __ballot_sync(0xffffffffu, nz);
    if (nz) {
      int p = pos + __popc(mk & ((1u << lane) - 1u));
      if (p < NPACK)  // hard fault guard (pool has 2x expected headroom)
        g_packed[p] = (unsigned short)(idx | (q < 0.f ? 0x8000u : 0u));
    }
    pos += __popc(mk);
  }
}

// ---------------- main fused kernel ----------------
// smem: stage0/1 (32x256 f32 ea), xT (256x32 f32 swizzled), hT/h2T/h3T (u8),
// sE (packed u16 pool), sB (boundaries). Total 160256 B.
#define SMEM_BYTES 160256

__device__ __forceinline__ void prefetch(const float* xblk, int c, float* stg,
                                         int tid) {
  const float* src = xblk + c * 256;
#pragma unroll
  for (int i = 0; i < 8; ++i) {
    int f4 = tid + 256 * i;            // 0..2047
    int row = f4 >> 6, c4 = f4 & 63;
    const float* g = src + row * 4096 + c4 * 4;
    unsigned sa = (unsigned)__cvta_generic_to_shared(stg + row * 256 + c4 * 4);
    asm volatile("cp.async.cg.shared.global [%0], [%1], 16;\n" :: "r"(sa), "l"(g));
  }
  asm volatile("cp.async.commit_group;\n");
}

__global__ void __launch_bounds__(256, 1) k_main(
    const float* __restrict__ x,
    const float* __restrict__ b1a, const float* __restrict__ b1b,
    const float* __restrict__ b2,  const float* __restrict__ b3,
    float* __restrict__ out) {
  extern __shared__ char smraw[];
  float* stage0 = (float*)smraw;                    // 32768 B
  float* stage1 = stage0 + 8192;                    // 32768 B
  float* xT     = stage1 + 8192;                    // 32768 B
  unsigned char* hT  = (unsigned char*)(xT + 8192); // 16384 B
  unsigned char* h2T = hT + 16384;                  // 4096 B
  unsigned char* h3T = h2T + 4096;                  // 2048 B
  unsigned short* sE = (unsigned short*)(h3T + 2048);   // 32768 B
  int* sB = (int*)(sE + NPACK);                     // 6656 B
  float* outT = (float*)hT;                         // alias (hT dead by layer 4)

  int tid = threadIdx.x, lane = tid & 31, warp = tid >> 5;
  const float* xblk = x + (size_t)blockIdx.x * 32 * 4096;

  prefetch(xblk, 0, stage0, tid);
  prefetch(xblk, 1, stage1, tid);

  // copy index pool + boundaries into smem (uint4 coalesced)
  {
    const uint4* gp = (const uint4*)g_packed;
    uint4* sp = (uint4*)sE;
    for (int i = tid; i < NPACK / 8; i += 256) sp[i] = gp[i];
    const uint4* gb = (const uint4*)g_bnd;
    uint4* sb = (uint4*)sB;
    for (int i = tid; i < NBND_AL / 4; i += 256) sb[i] = gb[i];
  }

  float acc[16];
#pragma unroll 1
  for (int c = 0; c < 16; ++c) {
    int br = c >> 2, sub = c & 3;
    float* stg = (c & 1) ? stage1 : stage0;
    if (c < 15) asm volatile("cp.async.wait_group 1;\n" ::: "memory");
    else        asm volatile("cp.async.wait_group 0;\n" ::: "memory");
    __syncthreads();

    // transpose 32x256 -> swizzled xT (conflict-free both sides)
#pragma unroll
    for (int i = 0; i < 32; ++i) {
      int q = warp + 8 * i;            // 0..255
      int row = q & 31, cb = q >> 5;
      int col = cb * 32 + lane;
      xT[col * 32 + (row ^ lane)] = stg[row * 256 + col];
    }
    __syncthreads();
    if (c + 2 < 16) prefetch(xblk, c + 2, stg, tid);

    if (sub == 0) {
#pragma unroll
      for (int j0 = 0; j0 < 16; ++j0) acc[j0] = 0.f;
    }
    const int* bnd = sB + ((br & 1) ? BND1B : BND1A);
#pragma unroll
    for (int j0 = 0; j0 < 16; ++j0) {
      int j = warp * 16 + j0;
      int k = bnd[j * 5 + sub], k1 = bnd[j * 5 + sub + 1];
      float a0 = 0.f, a1 = 0.f;
      for (; k + 2 <= k1; k += 2) {
        unsigned e0 = sE[k], e1 = sE[k + 1];
        float v0 = xT[(e0 & 255u) * 32u + (lane ^ (e0 & 31u))];
        float v1 = xT[(e1 & 255u) * 32u + (lane ^ (e1 & 31u))];
        a0 += (e0 & 0x8000u) ? -v0 : v0;
        a1 += (e1 & 0x8000u) ? -v1 : v1;
      }
      if (k < k1) {
        unsigned e0 = sE[k];
        float v0 = xT[(e0 & 255u) * 32u + (lane ^ (e0 & 31u))];
        a0 += (e0 & 0x8000u) ? -v0 : v0;
      }
      acc[j0] += a0 + a1;
    }
    if (sub == 3) {                    // finish branch: bias + quant_relu
      const float* bb = (br & 1) ? b1b : b1a;
      float s = __uint_as_float(g_sbits[br & 1]);
#pragma unroll
      for (int j0 = 0; j0 < 16; ++j0) {
        int j = warp * 16 + j0;
        float z = s * acc[j0] + bb[j];
        float n = fminf(fmaxf(rintf(z / ACT_F), 0.f), 3.f);
        hT[(br * 128 + j) * 32 + lane] = (unsigned char)n;
      }
    }
    __syncthreads();
  }

  // layer 2: 512 -> 128
  {
    float s2 = __uint_as_float(g_sbits[2]);
#pragma unroll
    for (int j0 = 0; j0 < 16; ++j0) {
      int j = warp * 16 + j0;
      int k = sB[OFF2 + j], k1 = sB[OFF2 + j + 1];
      int m0 = 0, m1 = 0;
      for (; k + 2 <= k1; k += 2) {
        unsigned e0 = sE[k], e1 = sE[k + 1];
        int v0 = hT[(e0 & 511u) * 32u + lane];
        int v1 = hT[(e1 & 511u) * 32u + lane];
        m0 += (e0 & 0x8000u) ? -v0 : v0;
        m1 += (e1 & 0x8000u) ? -v1 : v1;
      }
      if (k < k1) {
        unsigned e0 = sE[k];
        int v0 = hT[(e0 & 511u) * 32u + lane];
        m0 += (e0 & 0x8000u) ? -v0 : v0;
      }
      float z = s2 * (ACT_F * (float)(m0 + m1)) + b2[j];
      float n = fminf(fmaxf(rintf(z / ACT_F), 0.f), 3.f);
      h2T[j * 32 + lane] = (unsigned char)n;
    }
  }
  __syncthreads();
  // layer 3: 128 -> 64
  {
    float s3 = __uint_as_float(g_sbits[3]);
#pragma unroll
    for (int j0 = 0; j0 < 8; ++j0) {
      int j = warp * 8 + j0;
      int k = sB[OFF3 + j], k1 = sB[OFF3 + j + 1];
      int m = 0;
      for (; k < k1; ++k) {
        unsigned e = sE[k];
        int v = h2T[(e & 127u) * 32u + lane];
        m += (e & 0x8000u) ? -v : v;
      }
      float z = s3 * (ACT_F * (float)m) + b3[j];
      float n = fminf(fmaxf(rintf(z / ACT_F), 0.f), 3.f);
      h3T[j * 32 + lane] = (unsigned char)n;
    }
  }
  __syncthreads();
  // layer 4: 64 -> 128 (no bias, no quant)
  {
    float s4 = __uint_as_float(g_sbits[4]);
#pragma unroll
    for (int j0 = 0; j0 < 16; ++j0) {
      int j = warp * 16 + j0;
      int k = sB[OFF4 + j], k1 = sB[OFF4 + j + 1];
      int m = 0;
      for (; k < k1; ++k) {
        unsigned e = sE[k];
        int v = h3T[(e & 63u) * 32u + lane];
        m += (e & 0x8000u) ? -v : v;
      }
      outT[j * 33 + lane] = s4 * (ACT_F * (float)m);
    }
  }
  __syncthreads();
  float* og = out + (size_t)blockIdx.x * 32 * 128;
#pragma unroll
  for (int p = 0; p < 16; ++p) {
    int lin = tid + 256 * p;
    int row = lin >> 7, col = lin & 127;
    og[row * 128 + col] = outT[col * 33 + row];
  }
}

extern "C" void kernel_launch(void* const* d_in, const int* in_sizes, int n_in,
                              void* d_out, int out_size) {
  const float* x   = (const float*)d_in[0];
  const float* W1a = (const float*)d_in[1];
  const float* b1a = (const float*)d_in[2];
  const float* W1b = (const float*)d_in[3];
  const float* b1b = (const float*)d_in[4];
  const float* W2  = (const float*)d_in[5];
  const float* b2  = (const float*)d_in[6];
  const float* W3  = (const float*)d_in[7];
  const float* b3  = (const float*)d_in[8];
  const float* W4  = (const float*)d_in[9];
  float* out = (float*)d_out;

  cudaFuncSetAttribute(k_main, cudaFuncAttributeMaxDynamicSharedMemorySize,
                       SMEM_BYTES);
  k_init<<<1, 32>>>();
  k_scales<<<80, 256>>>(W1a, W1b, W2, W3, W4);
  k_count<<<72, 256>>>(W1a, W1b, W2, W3, W4);
  k_offsets<<<1, 256>>>();
  k_fill<<<72, 256>>>(W1a, W1b, W2, W3, W4);
  k_main<<<1024, 256, SMEM_BYTES>>>(x, b1a, b1b, b2, b3, out);
}

// round 5
// speedup vs baseline: 2.3724x; 1.9082x over previous
#include <cuda_runtime.h>
#include <cstdint>

#define ACT_F (4.0f/3.0f)

// ---- layer-1 streams: 64 slots (warp 0..7 x c8 0..7), each 68 t-packs x 16 u16
#define SLOT_U16 1088
#define SLOT_LMAX 66
#define DUMMY_ENT 8448      // col 256 * 33 -> zeroed pad slot in xT

__device__ unsigned g_sbits[5];
__device__ __align__(16) unsigned short g_stream[64 * SLOT_U16];
__device__ int g_T1[64];
__device__ __align__(16) unsigned short g_pool2[4096];
__device__ __align__(16) int g_bnd2[324];
__device__ int g_cnt234[320];

// ---------------- prep 0 ----------------
__global__ void k_init() { if (threadIdx.x < 5) g_sbits[threadIdx.x] = 0u; }

// ---------------- prep 1: per-matrix max|w| ----------------
__global__ void k_scales(const float* W1a, const float* W1b, const float* W2,
                         const float* W3, const float* W4) {
  __shared__ float red[8];
  const float* ptrs[5] = {W1a, W1b, W2, W3, W4};
  const int ns[5] = {131072, 131072, 65536, 8192, 8192};
  int m = blockIdx.x >> 4, slice = blockIdx.x & 15;
  int n4 = ns[m] >> 2;
  int per = (n4 + 15) >> 4;
  int lo = slice * per;
  int hi = lo + per; if (hi > n4) hi = n4;
  const float4* p = (const float4*)ptrs[m];
  float mx = 0.f;
  for (int i = lo + threadIdx.x; i < hi; i += 256) {
    float4 v = p[i];
    mx = fmaxf(mx, fmaxf(fmaxf(fabsf(v.x), fabsf(v.y)), fmaxf(fabsf(v.z), fabsf(v.w))));
  }
  for (int o = 16; o; o >>= 1) mx = fmaxf(mx, __shfl_xor_sync(0xffffffffu, mx, o));
  if ((threadIdx.x & 31) == 0) red[threadIdx.x >> 5] = mx;
  __syncthreads();
  if (threadIdx.x < 8) {
    mx = red[threadIdx.x];
    for (int o = 4; o; o >>= 1) mx = fmaxf(mx, __shfl_xor_sync(0xffu, mx, o));
    if (threadIdx.x == 0) atomicMax(&g_sbits[m], __float_as_uint(mx));
  }
}

// ---------------- prep 2: layer-1 interleaved padded streams ----------------
// 64 warps; warp gw builds slot (w = gw>>3, c8 = gw&7), c8 = mat*4 + chunk.
__global__ void k_build1(const float* W1a, const float* W1b) {
  int wl = threadIdx.x >> 5, lane = threadIdx.x & 31;
  int gw = blockIdx.x * 4 + wl;
  int w = gw >> 3, c8 = gw & 7;
  int mat = c8 >> 2, cl = c8 & 3;
  const float* W = mat ? W1b : W1a;
  float s = __uint_as_float(g_sbits[mat]);
  unsigned short* slot = g_stream + gw * SLOT_U16;
  int lens[16];
  int maxlen = 0;
#pragma unroll 1
  for (int j0 = 0; j0 < 16; ++j0) {
    const float* wr = W + (w * 16 + j0) * 1024 + cl * 256;
    int p = 0;
    for (int t = 0; t < 8; ++t) {
      int col = t * 32 + lane;
      float q = rintf(wr[col] / s);
      bool nz = (q != 0.f);
      unsigned mk = __ballot_sync(0xffffffffu, nz);
      if (nz) {
        int pos = p + __popc(mk & ((1u << lane) - 1u));
        if (pos < SLOT_LMAX)
          slot[pos * 16 + j0] =
              (unsigned short)((col * 33) | (q < 0.f ? 0x8000u : 0u));
      }
      p += __popc(mk);
    }
    if (p > SLOT_LMAX) p = SLOT_LMAX;
    lens[j0] = p;
    maxlen = maxlen > p ? maxlen : p;
  }
  int T = (maxlen + 1) & ~1;
#pragma unroll 1
  for (int j0 = 0; j0 < 16; ++j0)
    for (int p = lens[j0] + lane; p < T; p += 32)
      slot[p * 16 + j0] = (unsigned short)DUMMY_ENT;
  if (lane == 0) g_T1[gw] = T;
}

// ---------------- prep 3-5: layers 2-4 CSR (count / scan / fill) ----------------
__device__ __forceinline__ void decode234(int gw, const float* W2, const float* W3,
                                          const float* W4, const float*& W,
                                          int& row, int& len, int& m) {
  if (gw < 128)      { m = 2; row = gw;       len = 512; W = W2; }
  else if (gw < 192) { m = 3; row = gw - 128; len = 128; W = W3; }
  else               { m = 4; row = gw - 192; len = 64;  W = W4; }
}

__global__ void k_count2(const float* W2, const float* W3, const float* W4) {
  int gw = blockIdx.x * 8 + (threadIdx.x >> 5);
  int lane = threadIdx.x & 31;
  const float* W; int row, len, m;
  decode234(gw, W2, W3, W4, W, row, len, m);
  float s = __uint_as_float(g_sbits[m]);
  const float* wr = W + row * len;
  int c = 0;
  for (int t = 0; t < len / 32; ++t) {
    float q = rintf(wr[t * 32 + lane] / s);
    unsigned mk = __ballot_sync(0xffffffffu, q != 0.f);
    c += __popc(mk);
  }
  if (lane == 0) g_cnt234[gw] = c;
}

__global__ void k_offsets2() {
  __shared__ int sc[320];
  int tid = threadIdx.x;
  for (int i = tid; i < 320; i += 256) sc[i] = g_cnt234[i];
  __syncthreads();
  if (tid == 0) {
    int run = 0;
    for (int i = 0; i < 320; ++i) { run += sc[i]; sc[i] = run; }
  }
  __syncthreads();
  if (tid == 0) g_bnd2[0] = 0;
  for (int k = tid + 1; k <= 320; k += 256) g_bnd2[k] = sc[k - 1];
  if (tid < 3) g_bnd2[321 + tid] = 0;
}

__global__ void k_fill2(const float* W2, const float* W3, const float* W4) {
  int gw = blockIdx.x * 8 + (threadIdx.x >> 5);
  int lane = threadIdx.x & 31;
  const float* W; int row, len, m;
  decode234(gw, W2, W3, W4, W, row, len, m);
  float s = __uint_as_float(g_sbits[m]);
  const float* wr = W + row * len;
  int pos = g_bnd2[gw];
  for (int t = 0; t < len / 32; ++t) {
    int idx = t * 32 + lane;
    float q = rintf(wr[idx] / s);
    bool nz = (q != 0.f);
    unsigned mk = __ballot_sync(0xffffffffu, nz);
    if (nz) {
      int p = pos + __popc(mk & ((1u << lane) - 1u));
      if (p < 4096)
        g_pool2[p] = (unsigned short)(idx | (q < 0.f ? 0x8000u : 0u));
    }
    pos += __popc(mk);
  }
}

// ---------------- main fused kernel, occupancy 2 ----------------
// smem: xT0/xT1 (8480 f32 ea, stride-33 padded + dummy col), hT/h2T/h3T (u8),
// sE2 pool, sBnd, sT1.  Total 100,208 B -> 2 CTAs/SM.
#define XT0_OFF  0
#define XT1_OFF  33920
#define HT_OFF   67840
#define H2T_OFF  84256
#define H3T_OFF  88384
#define SE2_OFF  90464
#define SBND_OFF 98656
#define ST1_OFF  99952
#define SMEM_BYTES 100208

#define ENT2(r, J) do {                                                        \
    unsigned _o0 = (r) & 0x3FFFu;                                              \
    float _v0 = curl[_o0];                                                     \
    _v0 = __uint_as_float(__float_as_uint(_v0) ^ (((r) << 16) & 0x80000000u)); \
    acc[J] += _v0;                                                             \
    unsigned _o1 = ((r) >> 16) & 0x3FFFu;                                      \
    float _v1 = curl[_o1];                                                     \
    _v1 = __uint_as_float(__float_as_uint(_v1) ^ ((r) & 0x80000000u));         \
    acc[(J) + 1] += _v1;                                                       \
  } while (0)

#define PROC16(A0, A1)                                              \
  ENT2((A0).x, 0);  ENT2((A0).y, 2);  ENT2((A0).z, 4);  ENT2((A0).w, 6); \
  ENT2((A1).x, 8);  ENT2((A1).y, 10); ENT2((A1).z, 12); ENT2((A1).w, 14);

__global__ void __launch_bounds__(256, 2) k_main(
    const float* __restrict__ x,
    const float* __restrict__ b1a, const float* __restrict__ b1b,
    const float* __restrict__ b2,  const float* __restrict__ b3,
    float* __restrict__ out) {
  extern __shared__ char smraw[];
  float* xT0 = (float*)(smraw + XT0_OFF);
  float* xT1 = (float*)(smraw + XT1_OFF);
  unsigned char* hT  = (unsigned char*)(smraw + HT_OFF);
  unsigned char* h2T = (unsigned char*)(smraw + H2T_OFF);
  unsigned char* h3T = (unsigned char*)(smraw + H3T_OFF);
  unsigned short* sE2 = (unsigned short*)(smraw + SE2_OFF);
  int* sBnd = (int*)(smraw + SBND_OFF);
  int* sT1  = (int*)(smraw + ST1_OFF);
  float* outT = (float*)hT;   // alias; hT/h2T dead by layer 4

  int tid = threadIdx.x, lane = tid & 31, warp = tid >> 5;
  const float* xblk = x + (size_t)blockIdx.x * 32 * 4096;

  // smem metadata copies
  {
    const uint4* gp = (const uint4*)g_pool2;
    uint4* sp = (uint4*)sE2;
    for (int i = tid; i < 512; i += 256) sp[i] = gp[i];
    const uint4* gb = (const uint4*)g_bnd2;
    uint4* sb = (uint4*)sBnd;
    for (int i = tid; i < 81; i += 256) sb[i] = gb[i];
    const uint4* gt = (const uint4*)g_T1;
    uint4* st = (uint4*)sT1;
    for (int i = tid; i < 16; i += 256) st[i] = gt[i];
  }

  float v[32];
  // prologue: chunk 0 -> xT0
  {
    const float* xc = xblk;
#pragma unroll
    for (int it = 0; it < 32; ++it)
      v[it] = __ldg(xc + (warp * 4 + (it >> 3)) * 4096 + (it & 7) * 32 + lane);
#pragma unroll
    for (int it = 0; it < 32; ++it)
      xT0[((it & 7) * 32 + lane) * 33 + (warp * 4 + (it >> 3))] = v[it];
  }
  if (tid < 32) { xT0[8448 + tid] = 0.f; xT1[8448 + tid] = 0.f; }
  __syncthreads();

  float acc[16];
#pragma unroll 1
  for (int c = 0; c < 16; ++c) {
    float* cur = (c & 1) ? xT1 : xT0;
    float* nxt = (c & 1) ? xT0 : xT1;
    const float* curl = cur + lane;
    if (c < 15) {
      const float* xc = xblk + (c + 1) * 256;
#pragma unroll
      for (int it = 0; it < 32; ++it)
        v[it] = __ldg(xc + (warp * 4 + (it >> 3)) * 4096 + (it & 7) * 32 + lane);
    }
    if ((c & 3) == 0) {
#pragma unroll
      for (int j = 0; j < 16; ++j) acc[j] = 0.f;
    }
    {
      int slot = warp * 8 + (c & 7);
      const uint4* sp = (const uint4*)(g_stream + slot * SLOT_U16);
      int T = sT1[slot];
      uint4 a0 = sp[0], a1 = sp[1], b0 = sp[2], b1 = sp[3];
#pragma unroll 1
      for (int t = 0; t < T; t += 2) {
        uint4 n0 = sp[2 * t + 4], n1 = sp[2 * t + 5];
        uint4 n2 = sp[2 * t + 6], n3 = sp[2 * t + 7];
        PROC16(a0, a1);
        PROC16(b0, b1);
        a0 = n0; a1 = n1; b0 = n2; b1 = n3;
      }
    }
    if ((c & 3) == 3) {                 // end of branch: bias + quant_relu
      int br = c >> 2;
      const float* bb = (br & 1) ? b1b : b1a;
      float s = __uint_as_float(g_sbits[br & 1]);
#pragma unroll
      for (int j0 = 0; j0 < 16; ++j0) {
        int j = warp * 16 + j0;
        float z = s * acc[j0] + __ldg(bb + j);
        float n = fminf(fmaxf(rintf(z / ACT_F), 0.f), 3.f);
        hT[(br * 128 + j) * 32 + lane] = (unsigned char)n;
      }
    }
    if (c < 15) {
#pragma unroll
      for (int it = 0; it < 32; ++it)
        nxt[((it & 7) * 32 + lane) * 33 + (warp * 4 + (it >> 3))] = v[it];
    }
    __syncthreads();
  }

  // layer 2: 512 -> 128
  {
    float s2 = __uint_as_float(g_sbits[2]);
#pragma unroll
    for (int j0 = 0; j0 < 16; ++j0) {
      int j = warp * 16 + j0;
      int k = sBnd[j], k1 = sBnd[j + 1];
      int m0 = 0, m1 = 0;
      for (; k + 2 <= k1; k += 2) {
        unsigned e0 = sE2[k], e1 = sE2[k + 1];
        int v0 = hT[(e0 & 511u) * 32u + lane];
        int v1 = hT[(e1 & 511u) * 32u + lane];
        m0 += (e0 & 0x8000u) ? -v0 : v0;
        m1 += (e1 & 0x8000u) ? -v1 : v1;
      }
      if (k < k1) {
        unsigned e0 = sE2[k];
        int v0 = hT[(e0 & 511u) * 32u + lane];
        m0 += (e0 & 0x8000u) ? -v0 : v0;
      }
      float z = s2 * (ACT_F * (float)(m0 + m1)) + __ldg(b2 + j);
      float n = fminf(fmaxf(rintf(z / ACT_F), 0.f), 3.f);
      h2T[j * 32 + lane] = (unsigned char)n;
    }
  }
  __syncthreads();
  // layer 3: 128 -> 64
  {
    float s3 = __uint_as_float(g_sbits[3]);
#pragma unroll
    for (int j0 = 0; j0 < 8; ++j0) {
      int j = warp * 8 + j0;
      int k = sBnd[128 + j], k1 = sBnd[128 + j + 1];
      int m = 0;
      for (; k < k1; ++k) {
        unsigned e = sE2[k];
        int vv = h2T[(e & 127u) * 32u + lane];
        m += (e & 0x8000u) ? -vv : vv;
      }
      float z = s3 * (ACT_F * (float)m) + __ldg(b3 + j);
      float n = fminf(fmaxf(rintf(z / ACT_F), 0.f), 3.f);
      h3T[j * 32 + lane] = (unsigned char)n;
    }
  }
  __syncthreads();
  // layer 4: 64 -> 128 (no bias, no quant)
  {
    float s4 = __uint_as_float(g_sbits[4]);
#pragma unroll
    for (int j0 = 0; j0 < 16; ++j0) {
      int j = warp * 16 + j0;
      int k = sBnd[192 + j], k1 = sBnd[192 + j + 1];
      int m = 0;
      for (; k < k1; ++k) {
        unsigned e = sE2[k];
        int vv = h3T[(e & 63u) * 32u + lane];
        m += (e & 0x8000u) ? -vv : vv;
      }
      outT[j * 33 + lane] = s4 * (ACT_F * (float)m);
    }
  }
  __syncthreads();
  float* og = out + (size_t)blockIdx.x * 32 * 128;
#pragma unroll
  for (int p = 0; p < 16; ++p) {
    int lin = tid + 256 * p;
    int row = lin >> 7, col = lin & 127;
    og[row * 128 + col] = outT[col * 33 + row];
  }
}

extern "C" void kernel_launch(void* const* d_in, const int* in_sizes, int n_in,
                              void* d_out, int out_size) {
  const float* x   = (const float*)d_in[0];
  const float* W1a = (const float*)d_in[1];
  const float* b1a = (const float*)d_in[2];
  const float* W1b = (const float*)d_in[3];
  const float* b1b = (const float*)d_in[4];
  const float* W2  = (const float*)d_in[5];
  const float* b2  = (const float*)d_in[6];
  const float* W3  = (const float*)d_in[7];
  const float* b3  = (const float*)d_in[8];
  const float* W4  = (const float*)d_in[9];
  float* out = (float*)d_out;

  cudaFuncSetAttribute(k_main, cudaFuncAttributeMaxDynamicSharedMemorySize,
                       SMEM_BYTES);
  k_init<<<1, 32>>>();
  k_scales<<<80, 256>>>(W1a, W1b, W2, W3, W4);
  k_build1<<<16, 128>>>(W1a, W1b);
  k_count2<<<40, 256>>>(W2, W3, W4);
  k_offsets2<<<1, 256>>>();
  k_fill2<<<40, 256>>>(W2, W3, W4);
  k_main<<<1024, 256, SMEM_BYTES>>>(x, b1a, b1b, b2, b3, out);
}